// round 1
// baseline (speedup 1.0000x reference)
#include <cuda_runtime.h>
#include <math.h>

#define SS   4096      // 64*64
#define SSS  262144    // 64^3
#define CH   64

// Scratch (device globals — no allocation anywhere)
__device__ float g_att1[2*64*262144];
__device__ float g_att2[2*64*262144];
__device__ float g_pooled[2*2*262144];
__device__ float g_gate[2*2*262144];

// ---------------- conv1: depthwise 5x5x5, pad 2 ----------------
// tile: z=8, y=16, x=16; thread computes a z-column of 8 outputs.
__global__ __launch_bounds__(256) void k_conv1(const float* __restrict__ x,
                                               const float* __restrict__ w1,
                                               const float* __restrict__ b1) {
    const int tile = blockIdx.x;                 // 128 tiles: tz(8) ty(4) tx(4)
    const int c = blockIdx.y, b = blockIdx.z;
    const int tz = tile >> 4, ty = (tile >> 2) & 3, tx = tile & 3;
    const int z0 = tz * 8, y0 = ty * 16, x0 = tx * 16;

    __shared__ float sh[12*20*20];
    __shared__ float swt[125];

    const int tid = threadIdx.y * 16 + threadIdx.x;
    const float* __restrict__ xc = x + (size_t)(b*CH + c) * SSS;

    if (tid < 125) swt[tid] = w1[c*125 + tid];

    for (int s = tid; s < 12*20*20; s += 256) {
        int sz = s / 400, r = s % 400, sy = r / 20, sx = r % 20;
        int gz = z0 - 2 + sz, gy = y0 - 2 + sy, gx = x0 - 2 + sx;
        float v = 0.f;
        if ((unsigned)gz < 64u && (unsigned)gy < 64u && (unsigned)gx < 64u)
            v = xc[gz*SS + gy*64 + gx];
        sh[s] = v;
    }
    __syncthreads();

    const int lx = threadIdx.x, ly = threadIdx.y;
    float acc[8];
    const float bias = b1[c];
#pragma unroll
    for (int z = 0; z < 8; z++) acc[z] = bias;

#pragma unroll 1
    for (int ky = 0; ky < 5; ky++) {
        const int rowb = (ly + ky) * 20 + lx;
#pragma unroll
        for (int kx = 0; kx < 5; kx++) {
            float col[12];
#pragma unroll
            for (int j = 0; j < 12; j++)
                col[j] = sh[j*400 + rowb + kx];
#pragma unroll
            for (int kz = 0; kz < 5; kz++) {
                const float w = swt[kz*25 + ky*5 + kx];
#pragma unroll
                for (int z = 0; z < 8; z++)
                    acc[z] = fmaf(col[z+kz], w, acc[z]);
            }
        }
    }

    float* __restrict__ oc = g_att1 + (size_t)(b*CH + c) * SSS;
#pragma unroll
    for (int z = 0; z < 8; z++)
        oc[(z0+z)*SS + (y0+ly)*64 + (x0+lx)] = acc[z];
}

// ---------------- conv2: depthwise 7x7x7, dilation 3, pad 9 ----------------
// Residue decomposition: for p === r (mod 3) this is a DENSE 7-tap conv on the
// subsampled grid (len 22 for r=0, else 21), pad 3 in subgrid coords.
// Block: one (residue triple, 8x8 yx-subtile); 128 threads = 2 z-halves x 8 x 8.
__global__ __launch_bounds__(128) void k_conv2(const float* __restrict__ w2,
                                               const float* __restrict__ b2) {
    const int blk = blockIdx.x;                  // 27 residues * 9 yx tiles = 243
    const int c = blockIdx.y, b = blockIdx.z;
    const int res = blk / 9, t = blk % 9;
    const int rz = res / 9, ry = (res / 3) % 3, rx = res % 3;
    const int tyi = t / 3, txi = t % 3;
    const int Lz = (rz == 0) ? 22 : 21;
    const int Ly = (ry == 0) ? 22 : 21;
    const int Lx = (rx == 0) ? 22 : 21;

    __shared__ float sh[28*14*14];               // subgrid z:-3..24, y/x: tile-3..tile+10
    __shared__ float swt[343];
    const int tid = threadIdx.x;

    const float* __restrict__ icp = g_att1 + (size_t)(b*CH + c) * SSS;
    for (int s = tid; s < 343; s += 128) swt[s] = w2[c*343 + s];

    const int uy0 = tyi*8, ux0 = txi*8;
    for (int s = tid; s < 28*14*14; s += 128) {
        int sz = s / 196, r = s % 196, sy = r / 14, sx = r % 14;
        int gz = rz + 3*(sz - 3);
        int gy = ry + 3*(uy0 + sy - 3);
        int gx = rx + 3*(ux0 + sx - 3);
        float v = 0.f;
        if ((unsigned)gz < 64u && (unsigned)gy < 64u && (unsigned)gx < 64u)
            v = icp[gz*SS + gy*64 + gx];
        sh[s] = v;
    }
    __syncthreads();

    const int h  = tid >> 6;                     // z half: 0 -> u 0..10, 1 -> u 11..21
    const int ly = (tid >> 3) & 7, lx = tid & 7;
    const int uy = uy0 + ly, ux = ux0 + lx;
    const int zb = 11*h;

    float acc[11];
    const float bias = b2[c];
#pragma unroll
    for (int l = 0; l < 11; l++) acc[l] = bias;

#pragma unroll 1
    for (int ky = 0; ky < 7; ky++) {
        const int rowb = (ly + ky)*14 + lx;
#pragma unroll
        for (int kx = 0; kx < 7; kx++) {
            float col[17];
#pragma unroll
            for (int j = 0; j < 17; j++)
                col[j] = sh[(zb + j)*196 + rowb + kx];
#pragma unroll
            for (int kz = 0; kz < 7; kz++) {
                const float w = swt[kz*49 + ky*7 + kx];
#pragma unroll
                for (int l = 0; l < 11; l++)
                    acc[l] = fmaf(col[l+kz], w, acc[l]);
            }
        }
    }

    if (uy < Ly && ux < Lx) {
        float* __restrict__ oc = g_att2 + (size_t)(b*CH + c)*SSS;
        const int gy = ry + 3*uy, gx = rx + 3*ux;
#pragma unroll
        for (int l = 0; l < 11; l++) {
            const int u = zb + l;
            if (u < Lz)
                oc[(rz + 3*u)*SS + gy*64 + gx] = acc[l];
        }
    }
}

// ---------------- pool: channel mean + max over [att1; att2] ----------------
__global__ __launch_bounds__(256) void k_pool() {
    const int idx = blockIdx.x * 256 + threadIdx.x;     // over 2*SSS = 524288
    const int b = idx >> 18, s = idx & (SSS - 1);
    const float* p1 = g_att1 + (size_t)b*CH*SSS + s;
    const float* p2 = g_att2 + (size_t)b*CH*SSS + s;
    float sum = 0.f, mx = -INFINITY;
#pragma unroll 8
    for (int c = 0; c < 64; c++) { float v = p1[(size_t)c*SSS]; sum += v; mx = fmaxf(mx, v); }
#pragma unroll 8
    for (int c = 0; c < 64; c++) { float v = p2[(size_t)c*SSS]; sum += v; mx = fmaxf(mx, v); }
    g_pooled[(size_t)b*2*SSS + s]       = sum * (1.f/128.f);
    g_pooled[(size_t)b*2*SSS + SSS + s] = mx;
}

// ---------------- gate: 2->2 conv 7x7x7 pad 3, sigmoid ----------------
// tile: z=8, y=16, x=8; 128 threads; per-thread z-column, both output channels.
__global__ __launch_bounds__(128) void k_gate(const float* __restrict__ ws,
                                              const float* __restrict__ bs) {
    const int tile = blockIdx.x;                 // tz(8) ty(4) tx(8) = 256
    const int b = blockIdx.y;
    const int tz = tile >> 5, ty = (tile >> 3) & 3, tx = tile & 7;
    const int z0 = tz*8, y0 = ty*16, x0 = tx*8;

    __shared__ float sh[2*14*22*14];             // [ic][z14][y22][x14]
    __shared__ float swt[1372];
    const int tid = threadIdx.x;

    for (int s = tid; s < 1372; s += 128) swt[s] = ws[s];
    for (int s = tid; s < 2*14*22*14; s += 128) {
        int icc = s / 4312, r = s % 4312;
        int sz = r / 308, r2 = r % 308, sy = r2 / 14, sx = r2 % 14;
        int gz = z0-3+sz, gy = y0-3+sy, gx = x0-3+sx;
        float v = 0.f;
        if ((unsigned)gz < 64u && (unsigned)gy < 64u && (unsigned)gx < 64u)
            v = g_pooled[((size_t)b*2 + icc)*SSS + gz*SS + gy*64 + gx];
        sh[s] = v;
    }
    __syncthreads();

    const int ly = tid >> 3, lx = tid & 7;
    float acc0[8], acc1[8];
    const float bias0 = bs[0], bias1 = bs[1];
#pragma unroll
    for (int z = 0; z < 8; z++) { acc0[z] = bias0; acc1[z] = bias1; }

#pragma unroll 1
    for (int icc = 0; icc < 2; icc++)
#pragma unroll 1
    for (int ky = 0; ky < 7; ky++)
#pragma unroll 1
    for (int kx = 0; kx < 7; kx++) {
        float col[14];
#pragma unroll
        for (int j = 0; j < 14; j++)
            col[j] = sh[icc*4312 + j*308 + (ly+ky)*14 + lx + kx];
#pragma unroll
        for (int kz = 0; kz < 7; kz++) {
            const float w0 = swt[icc*343 + kz*49 + ky*7 + kx];
            const float w1 = swt[686 + icc*343 + kz*49 + ky*7 + kx];
#pragma unroll
            for (int z = 0; z < 8; z++) {
                acc0[z] = fmaf(col[z+kz], w0, acc0[z]);
                acc1[z] = fmaf(col[z+kz], w1, acc1[z]);
            }
        }
    }

    float* g0 = g_gate + (size_t)b*2*SSS;
#pragma unroll
    for (int z = 0; z < 8; z++) {
        const int o = (z0+z)*SS + (y0+ly)*64 + (x0+lx);
        g0[o]       = 1.f/(1.f + __expf(-acc0[z]));
        g0[SSS + o] = 1.f/(1.f + __expf(-acc1[z]));
    }
}

// ---------------- combine: out = att1*g0 + att2*g1 + x ----------------
__global__ __launch_bounds__(256) void k_combine(const float* __restrict__ x,
                                                 float* __restrict__ out) {
    const int i = blockIdx.x * 256 + threadIdx.x;       // float4 index, 8388608 total
    const size_t e = (size_t)i * 4;
    const int b = (int)(e >> 24);                        // 64*SSS = 2^24
    const int s = (int)(e & (SSS - 1));
    const float4 a1 = *(const float4*)(g_att1 + e);
    const float4 a2 = *(const float4*)(g_att2 + e);
    const float4 xv = *(const float4*)(x + e);
    const float4 g0 = *(const float4*)(g_gate + (size_t)b*2*SSS + s);
    const float4 g1 = *(const float4*)(g_gate + (size_t)b*2*SSS + SSS + s);
    float4 o;
    o.x = fmaf(a1.x, g0.x, fmaf(a2.x, g1.x, xv.x));
    o.y = fmaf(a1.y, g0.y, fmaf(a2.y, g1.y, xv.y));
    o.z = fmaf(a1.z, g0.z, fmaf(a2.z, g1.z, xv.z));
    o.w = fmaf(a1.w, g0.w, fmaf(a2.w, g1.w, xv.w));
    *(float4*)(out + e) = o;
}

extern "C" void kernel_launch(void* const* d_in, const int* in_sizes, int n_in,
                              void* d_out, int out_size) {
    const float* x  = (const float*)d_in[0];
    const float* w1 = (const float*)d_in[1];
    const float* b1 = (const float*)d_in[2];
    const float* w2 = (const float*)d_in[3];
    const float* b2 = (const float*)d_in[4];
    const float* ws = (const float*)d_in[5];
    const float* bs = (const float*)d_in[6];
    float* out = (float*)d_out;

    k_conv1<<<dim3(128, 64, 2), dim3(16, 16)>>>(x, w1, b1);
    k_conv2<<<dim3(243, 64, 2), 128>>>(w2, b2);
    k_pool<<<2048, 256>>>();
    k_gate<<<dim3(256, 2), 128>>>(ws, bs);
    k_combine<<<32768, 256>>>(x, out);
}

// round 2
// speedup vs baseline: 1.1744x; 1.1744x over previous
#include <cuda_runtime.h>
#include <math.h>

#define SS   4096      // 64*64
#define SSS  262144    // 64^3
#define CH   64

typedef unsigned long long u64;

// Scratch (device globals). att1/att2 are batch-interleaved: element (c*SSS+s)
// is a float2 = (batch0, batch1). Declared float4 for 16B base alignment.
__device__ float4 g_att1[CH*SSS/2];
__device__ float4 g_att2[CH*SSS/2];
__device__ float  g_pooled[2*2*SSS];   // [b][{mean,max}][s]
__device__ float  g_gate[2*2*SSS];     // [b][{g0,g1}][s]

__device__ __forceinline__ u64 pk2(float lo, float hi) {
    u64 r; asm("mov.b64 %0, {%1, %2};" : "=l"(r) : "f"(lo), "f"(hi)); return r;
}
__device__ __forceinline__ void ffma2(u64& d, u64 a, u64 b) {
    asm("fma.rn.f32x2 %0, %1, %2, %0;" : "+l"(d) : "l"(a), "l"(b));
}

// ---------------- conv1: depthwise 5x5x5, pad 2, both batches packed --------
// tile: z=8, y=16, x=16; thread computes a z-column of 8 packed outputs.
__global__ __launch_bounds__(256) void k_conv1(const float* __restrict__ x,
                                               const float* __restrict__ w1,
                                               const float* __restrict__ b1) {
    const int tile = blockIdx.x;                 // 128 tiles: tz(8) ty(4) tx(4)
    const int c = blockIdx.y;
    const int tz = tile >> 4, ty = (tile >> 2) & 3, tx = tile & 3;
    const int z0 = tz * 8, y0 = ty * 16, x0 = tx * 16;

    __shared__ float2 sh[12*20*20];              // 38.4 KB
    __shared__ float2 swt[125];

    const int tid = threadIdx.y * 16 + threadIdx.x;
    const float* __restrict__ x0p = x + (size_t)c * SSS;
    const float* __restrict__ x1p = x + (size_t)(CH + c) * SSS;

    if (tid < 125) { float w = w1[c*125 + tid]; swt[tid] = make_float2(w, w); }

    for (int s = tid; s < 12*20*20; s += 256) {
        int sz = s / 400, r = s % 400, sy = r / 20, sx = r % 20;
        int gz = z0 - 2 + sz, gy = y0 - 2 + sy, gx = x0 - 2 + sx;
        float2 v = make_float2(0.f, 0.f);
        if ((unsigned)gz < 64u && (unsigned)gy < 64u && (unsigned)gx < 64u) {
            int o = gz*SS + gy*64 + gx;
            v.x = x0p[o]; v.y = x1p[o];
        }
        sh[s] = v;
    }
    __syncthreads();

    const int lx = threadIdx.x, ly = threadIdx.y;
    u64 acc[8];
    const float bias = b1[c];
    const u64 bpk = pk2(bias, bias);
#pragma unroll
    for (int z = 0; z < 8; z++) acc[z] = bpk;

#pragma unroll 1
    for (int ky = 0; ky < 5; ky++) {
        const int rowb = (ly + ky) * 20 + lx;
#pragma unroll
        for (int kx = 0; kx < 5; kx++) {
            u64 col[12];
#pragma unroll
            for (int j = 0; j < 12; j++)
                col[j] = *(const u64*)&sh[j*400 + rowb + kx];
#pragma unroll
            for (int kz = 0; kz < 5; kz++) {
                const u64 w = *(const u64*)&swt[kz*25 + ky*5 + kx];
#pragma unroll
                for (int z = 0; z < 8; z++)
                    ffma2(acc[z], col[z+kz], w);
            }
        }
    }

    float2* __restrict__ oc = (float2*)g_att1 + (size_t)c * SSS;
#pragma unroll
    for (int z = 0; z < 8; z++)
        *(u64*)&oc[(z0+z)*SS + (y0+ly)*64 + (x0+lx)] = acc[z];
}

// ---------------- conv2: depthwise 7x7x7, dilation 3, pad 9 -----------------
// Residue decomposition (mod 3) -> dense 7-tap conv on subsampled grid.
// Both batches packed. Block: (residue triple, 8x8 yx subtile), 128 threads.
__global__ __launch_bounds__(128) void k_conv2(const float* __restrict__ w2,
                                               const float* __restrict__ b2) {
    const int blk = blockIdx.x;                  // 27 residues * 9 yx tiles
    const int c = blockIdx.y;
    const int res = blk / 9, t = blk % 9;
    const int rz = res / 9, ry = (res / 3) % 3, rx = res % 3;
    const int tyi = t / 3, txi = t % 3;
    const int Lz = (rz == 0) ? 22 : 21;
    const int Ly = (ry == 0) ? 22 : 21;
    const int Lx = (rx == 0) ? 22 : 21;

    __shared__ float2 sh[28*14*14];              // 43.9 KB
    __shared__ float2 swt[343];                  // 2.7 KB
    const int tid = threadIdx.x;

    const float2* __restrict__ icp = (const float2*)g_att1 + (size_t)c * SSS;
    for (int s = tid; s < 343; s += 128) { float w = w2[c*343 + s]; swt[s] = make_float2(w, w); }

    const int uy0 = tyi*8, ux0 = txi*8;
    for (int s = tid; s < 28*14*14; s += 128) {
        int sz = s / 196, r = s % 196, sy = r / 14, sx = r % 14;
        int gz = rz + 3*(sz - 3);
        int gy = ry + 3*(uy0 + sy - 3);
        int gx = rx + 3*(ux0 + sx - 3);
        float2 v = make_float2(0.f, 0.f);
        if ((unsigned)gz < 64u && (unsigned)gy < 64u && (unsigned)gx < 64u)
            v = icp[gz*SS + gy*64 + gx];
        sh[s] = v;
    }
    __syncthreads();

    const int h  = tid >> 6;                     // z half: u 0..10 / 11..21
    const int ly = (tid >> 3) & 7, lx = tid & 7;
    const int uy = uy0 + ly, ux = ux0 + lx;
    const int zb = 11*h;

    u64 acc[11];
    const float bias = b2[c];
    const u64 bpk = pk2(bias, bias);
#pragma unroll
    for (int l = 0; l < 11; l++) acc[l] = bpk;

#pragma unroll 1
    for (int ky = 0; ky < 7; ky++) {
        const int rowb = (ly + ky)*14 + lx;
#pragma unroll
        for (int kx = 0; kx < 7; kx++) {
            u64 col[17];
#pragma unroll
            for (int j = 0; j < 17; j++)
                col[j] = *(const u64*)&sh[(zb + j)*196 + rowb + kx];
#pragma unroll
            for (int kz = 0; kz < 7; kz++) {
                const u64 w = *(const u64*)&swt[kz*49 + ky*7 + kx];
#pragma unroll
                for (int l = 0; l < 11; l++)
                    ffma2(acc[l], col[l+kz], w);
            }
        }
    }

    if (uy < Ly && ux < Lx) {
        float2* __restrict__ oc = (float2*)g_att2 + (size_t)c*SSS;
        const int gy = ry + 3*uy, gx = rx + 3*ux;
#pragma unroll
        for (int l = 0; l < 11; l++) {
            const int u = zb + l;
            if (u < Lz)
                *(u64*)&oc[(rz + 3*u)*SS + gy*64 + gx] = acc[l];
        }
    }
}

// ---------------- pool: channel mean + max over [att1; att2], both batches --
__global__ __launch_bounds__(256) void k_pool() {
    const int s = blockIdx.x * 256 + threadIdx.x;       // over SSS
    const float2* p1 = (const float2*)g_att1 + s;
    const float2* p2 = (const float2*)g_att2 + s;
    float s0 = 0.f, s1 = 0.f, m0 = -INFINITY, m1 = -INFINITY;
#pragma unroll 8
    for (int c = 0; c < 64; c++) {
        float2 v = p1[(size_t)c*SSS];
        s0 += v.x; s1 += v.y; m0 = fmaxf(m0, v.x); m1 = fmaxf(m1, v.y);
    }
#pragma unroll 8
    for (int c = 0; c < 64; c++) {
        float2 v = p2[(size_t)c*SSS];
        s0 += v.x; s1 += v.y; m0 = fmaxf(m0, v.x); m1 = fmaxf(m1, v.y);
    }
    g_pooled[s]             = s0 * (1.f/128.f);
    g_pooled[SSS + s]       = m0;
    g_pooled[2*SSS + s]     = s1 * (1.f/128.f);
    g_pooled[3*SSS + s]     = m1;
}

// ---------------- gate: 2->2 conv 7x7x7 pad 3, sigmoid (scalar, per batch) --
__global__ __launch_bounds__(128) void k_gate(const float* __restrict__ ws,
                                              const float* __restrict__ bs) {
    const int tile = blockIdx.x;                 // tz(8) ty(4) tx(8) = 256
    const int b = blockIdx.y;
    const int tz = tile >> 5, ty = (tile >> 3) & 3, tx = tile & 7;
    const int z0 = tz*8, y0 = ty*16, x0 = tx*8;

    __shared__ float sh[2*14*22*14];
    __shared__ float swt[1372];
    const int tid = threadIdx.x;

    for (int s = tid; s < 1372; s += 128) swt[s] = ws[s];
    for (int s = tid; s < 2*14*22*14; s += 128) {
        int icc = s / 4312, r = s % 4312;
        int sz = r / 308, r2 = r % 308, sy = r2 / 14, sx = r2 % 14;
        int gz = z0-3+sz, gy = y0-3+sy, gx = x0-3+sx;
        float v = 0.f;
        if ((unsigned)gz < 64u && (unsigned)gy < 64u && (unsigned)gx < 64u)
            v = g_pooled[((size_t)b*2 + icc)*SSS + gz*SS + gy*64 + gx];
        sh[s] = v;
    }
    __syncthreads();

    const int ly = tid >> 3, lx = tid & 7;
    float acc0[8], acc1[8];
    const float bias0 = bs[0], bias1 = bs[1];
#pragma unroll
    for (int z = 0; z < 8; z++) { acc0[z] = bias0; acc1[z] = bias1; }

#pragma unroll 1
    for (int icc = 0; icc < 2; icc++)
#pragma unroll 1
    for (int ky = 0; ky < 7; ky++)
#pragma unroll 1
    for (int kx = 0; kx < 7; kx++) {
        float col[14];
#pragma unroll
        for (int j = 0; j < 14; j++)
            col[j] = sh[icc*4312 + j*308 + (ly+ky)*14 + lx + kx];
#pragma unroll
        for (int kz = 0; kz < 7; kz++) {
            const float w0 = swt[icc*343 + kz*49 + ky*7 + kx];
            const float w1 = swt[686 + icc*343 + kz*49 + ky*7 + kx];
#pragma unroll
            for (int z = 0; z < 8; z++) {
                acc0[z] = fmaf(col[z+kz], w0, acc0[z]);
                acc1[z] = fmaf(col[z+kz], w1, acc1[z]);
            }
        }
    }

    float* g0 = g_gate + (size_t)b*2*SSS;
#pragma unroll
    for (int z = 0; z < 8; z++) {
        const int o = (z0+z)*SS + (y0+ly)*64 + (x0+lx);
        g0[o]       = 1.f/(1.f + __expf(-acc0[z]));
        g0[SSS + o] = 1.f/(1.f + __expf(-acc1[z]));
    }
}

// ---------------- combine: out = att1*g0 + att2*g1 + x ----------------------
// Thread handles 2 consecutive s for one channel, both batches.
__global__ __launch_bounds__(256) void k_combine(const float* __restrict__ x,
                                                 float* __restrict__ out) {
    const int i = blockIdx.x * 256 + threadIdx.x;      // 8,388,608 threads
    const int c = i >> 17;                              // SSS/2 per channel
    const int s = (i & 131071) << 1;
    const float4 a1 = *(const float4*)((const float*)g_att1 + ((size_t)c*SSS + s)*2);
    const float4 a2 = *(const float4*)((const float*)g_att2 + ((size_t)c*SSS + s)*2);

    // batch 0
    {
        const float2 xv = *(const float2*)(x + (size_t)c*SSS + s);
        const float2 g0 = *(const float2*)(g_gate + s);
        const float2 g1 = *(const float2*)(g_gate + SSS + s);
        float2 o;
        o.x = fmaf(a1.x, g0.x, fmaf(a2.x, g1.x, xv.x));
        o.y = fmaf(a1.z, g0.y, fmaf(a2.z, g1.y, xv.y));
        *(float2*)(out + (size_t)c*SSS + s) = o;
    }
    // batch 1
    {
        const float2 xv = *(const float2*)(x + (size_t)(CH + c)*SSS + s);
        const float2 g0 = *(const float2*)(g_gate + 2*SSS + s);
        const float2 g1 = *(const float2*)(g_gate + 3*SSS + s);
        float2 o;
        o.x = fmaf(a1.y, g0.x, fmaf(a2.y, g1.x, xv.x));
        o.y = fmaf(a1.w, g0.y, fmaf(a2.w, g1.y, xv.y));
        *(float2*)(out + (size_t)(CH + c)*SSS + s) = o;
    }
}

extern "C" void kernel_launch(void* const* d_in, const int* in_sizes, int n_in,
                              void* d_out, int out_size) {
    const float* x  = (const float*)d_in[0];
    const float* w1 = (const float*)d_in[1];
    const float* b1 = (const float*)d_in[2];
    const float* w2 = (const float*)d_in[3];
    const float* b2 = (const float*)d_in[4];
    const float* ws = (const float*)d_in[5];
    const float* bs = (const float*)d_in[6];
    float* out = (float*)d_out;

    k_conv1<<<dim3(128, 64), dim3(16, 16)>>>(x, w1, b1);
    k_conv2<<<dim3(243, 64), 128>>>(w2, b2);
    k_pool<<<1024, 256>>>();
    k_gate<<<dim3(256, 2), 128>>>(ws, bs);
    k_combine<<<32768, 256>>>(x, out);
}

// round 3
// speedup vs baseline: 1.1748x; 1.0004x over previous
#include <cuda_runtime.h>
#include <math.h>

#define SS   4096      // 64*64
#define SSS  262144    // 64^3
#define CH   64

typedef unsigned long long u64;

// Scratch (device globals). att1/att2 are batch-interleaved: element (c*SSS+s)
// is a float2 = (batch0, batch1). Declared float4 for 16B base alignment.
__device__ float4 g_att1[CH*SSS/2];
__device__ float4 g_att2[CH*SSS/2];
__device__ float  g_pooled[2*2*SSS];   // [b][{mean,max}][s]
__device__ float  g_gate[2*2*SSS];     // [b][{g0,g1}][s]

__device__ __forceinline__ u64 pk2(float lo, float hi) {
    u64 r; asm("mov.b64 %0, {%1, %2};" : "=l"(r) : "f"(lo), "f"(hi)); return r;
}
__device__ __forceinline__ void ffma2(u64& d, u64 a, u64 b) {
    asm("fma.rn.f32x2 %0, %1, %2, %0;" : "+l"(d) : "l"(a), "l"(b));
}

// ---------------- conv1: depthwise 5x5x5, pad 2, both batches packed --------
// tile: z=8, y=16, x=16; thread computes a z-column of 8 packed outputs.
__global__ __launch_bounds__(256) void k_conv1(const float* __restrict__ x,
                                               const float* __restrict__ w1,
                                               const float* __restrict__ b1) {
    const int tile = blockIdx.x;                 // 128 tiles: tz(8) ty(4) tx(4)
    const int c = blockIdx.y;
    const int tz = tile >> 4, ty = (tile >> 2) & 3, tx = tile & 3;
    const int z0 = tz * 8, y0 = ty * 16, x0 = tx * 16;

    __shared__ float2 sh[12*20*20];              // 38.4 KB
    __shared__ float2 swt[125];

    const int tid = threadIdx.y * 16 + threadIdx.x;
    const float* __restrict__ x0p = x + (size_t)c * SSS;
    const float* __restrict__ x1p = x + (size_t)(CH + c) * SSS;

    if (tid < 125) { float w = w1[c*125 + tid]; swt[tid] = make_float2(w, w); }

    for (int s = tid; s < 12*20*20; s += 256) {
        int sz = s / 400, r = s % 400, sy = r / 20, sx = r % 20;
        int gz = z0 - 2 + sz, gy = y0 - 2 + sy, gx = x0 - 2 + sx;
        float2 v = make_float2(0.f, 0.f);
        if ((unsigned)gz < 64u && (unsigned)gy < 64u && (unsigned)gx < 64u) {
            int o = gz*SS + gy*64 + gx;
            v.x = x0p[o]; v.y = x1p[o];
        }
        sh[s] = v;
    }
    __syncthreads();

    const int lx = threadIdx.x, ly = threadIdx.y;
    u64 acc[8];
    const float bias = b1[c];
    const u64 bpk = pk2(bias, bias);
#pragma unroll
    for (int z = 0; z < 8; z++) acc[z] = bpk;

#pragma unroll 1
    for (int ky = 0; ky < 5; ky++) {
        const int rowb = (ly + ky) * 20 + lx;
#pragma unroll
        for (int kx = 0; kx < 5; kx++) {
            u64 col[12];
#pragma unroll
            for (int j = 0; j < 12; j++)
                col[j] = *(const u64*)&sh[j*400 + rowb + kx];
#pragma unroll
            for (int kz = 0; kz < 5; kz++) {
                const u64 w = *(const u64*)&swt[kz*25 + ky*5 + kx];
#pragma unroll
                for (int z = 0; z < 8; z++)
                    ffma2(acc[z], col[z+kz], w);
            }
        }
    }

    float2* __restrict__ oc = (float2*)g_att1 + (size_t)c * SSS;
#pragma unroll
    for (int z = 0; z < 8; z++)
        *(u64*)&oc[(z0+z)*SS + (y0+ly)*64 + (x0+lx)] = acc[z];
}

// ---------------- conv2: depthwise 7x7x7, dilation 3, pad 9 -----------------
// Residue decomposition (mod 3) -> dense 7-tap conv on subsampled grid.
// Both batches packed. Block: (residue triple, 8x8 yx subtile), 128 threads.
__global__ __launch_bounds__(128) void k_conv2(const float* __restrict__ w2,
                                               const float* __restrict__ b2) {
    const int blk = blockIdx.x;                  // 27 residues * 9 yx tiles
    const int c = blockIdx.y;
    const int res = blk / 9, t = blk % 9;
    const int rz = res / 9, ry = (res / 3) % 3, rx = res % 3;
    const int tyi = t / 3, txi = t % 3;
    const int Lz = (rz == 0) ? 22 : 21;
    const int Ly = (ry == 0) ? 22 : 21;
    const int Lx = (rx == 0) ? 22 : 21;

    __shared__ float2 sh[28*14*14];              // 43.9 KB
    __shared__ float2 swt[343];                  // 2.7 KB
    const int tid = threadIdx.x;

    const float2* __restrict__ icp = (const float2*)g_att1 + (size_t)c * SSS;
    for (int s = tid; s < 343; s += 128) { float w = w2[c*343 + s]; swt[s] = make_float2(w, w); }

    const int uy0 = tyi*8, ux0 = txi*8;
    for (int s = tid; s < 28*14*14; s += 128) {
        int sz = s / 196, r = s % 196, sy = r / 14, sx = r % 14;
        int gz = rz + 3*(sz - 3);
        int gy = ry + 3*(uy0 + sy - 3);
        int gx = rx + 3*(ux0 + sx - 3);
        float2 v = make_float2(0.f, 0.f);
        if ((unsigned)gz < 64u && (unsigned)gy < 64u && (unsigned)gx < 64u)
            v = icp[gz*SS + gy*64 + gx];
        sh[s] = v;
    }
    __syncthreads();

    const int h  = tid >> 6;                     // z half: u 0..10 / 11..21
    const int ly = (tid >> 3) & 7, lx = tid & 7;
    const int uy = uy0 + ly, ux = ux0 + lx;
    const int zb = 11*h;

    u64 acc[11];
    const float bias = b2[c];
    const u64 bpk = pk2(bias, bias);
#pragma unroll
    for (int l = 0; l < 11; l++) acc[l] = bpk;

#pragma unroll 1
    for (int ky = 0; ky < 7; ky++) {
        const int rowb = (ly + ky)*14 + lx;
#pragma unroll
        for (int kx = 0; kx < 7; kx++) {
            u64 col[17];
#pragma unroll
            for (int j = 0; j < 17; j++)
                col[j] = *(const u64*)&sh[(zb + j)*196 + rowb + kx];
#pragma unroll
            for (int kz = 0; kz < 7; kz++) {
                const u64 w = *(const u64*)&swt[kz*49 + ky*7 + kx];
#pragma unroll
                for (int l = 0; l < 11; l++)
                    ffma2(acc[l], col[l+kz], w);
            }
        }
    }

    if (uy < Ly && ux < Lx) {
        float2* __restrict__ oc = (float2*)g_att2 + (size_t)c*SSS;
        const int gy = ry + 3*uy, gx = rx + 3*ux;
#pragma unroll
        for (int l = 0; l < 11; l++) {
            const int u = zb + l;
            if (u < Lz)
                *(u64*)&oc[(rz + 3*u)*SS + gy*64 + gx] = acc[l];
        }
    }
}

// ---------------- pool: channel mean + max over [att1; att2], both batches --
__global__ __launch_bounds__(256) void k_pool() {
    const int s = blockIdx.x * 256 + threadIdx.x;       // over SSS
    const float2* p1 = (const float2*)g_att1 + s;
    const float2* p2 = (const float2*)g_att2 + s;
    float s0 = 0.f, s1 = 0.f, m0 = -INFINITY, m1 = -INFINITY;
#pragma unroll 8
    for (int c = 0; c < 64; c++) {
        float2 v = p1[(size_t)c*SSS];
        s0 += v.x; s1 += v.y; m0 = fmaxf(m0, v.x); m1 = fmaxf(m1, v.y);
    }
#pragma unroll 8
    for (int c = 0; c < 64; c++) {
        float2 v = p2[(size_t)c*SSS];
        s0 += v.x; s1 += v.y; m0 = fmaxf(m0, v.x); m1 = fmaxf(m1, v.y);
    }
    g_pooled[s]             = s0 * (1.f/128.f);
    g_pooled[SSS + s]       = m0;
    g_pooled[2*SSS + s]     = s1 * (1.f/128.f);
    g_pooled[3*SSS + s]     = m1;
}

// ---------------- gate: 2->2 conv 7x7x7 pad 3, sigmoid (scalar, per batch) --
__global__ __launch_bounds__(128) void k_gate(const float* __restrict__ ws,
                                              const float* __restrict__ bs) {
    const int tile = blockIdx.x;                 // tz(8) ty(4) tx(8) = 256
    const int b = blockIdx.y;
    const int tz = tile >> 5, ty = (tile >> 3) & 3, tx = tile & 7;
    const int z0 = tz*8, y0 = ty*16, x0 = tx*8;

    __shared__ float sh[2*14*22*14];
    __shared__ float swt[1372];
    const int tid = threadIdx.x;

    for (int s = tid; s < 1372; s += 128) swt[s] = ws[s];
    for (int s = tid; s < 2*14*22*14; s += 128) {
        int icc = s / 4312, r = s % 4312;
        int sz = r / 308, r2 = r % 308, sy = r2 / 14, sx = r2 % 14;
        int gz = z0-3+sz, gy = y0-3+sy, gx = x0-3+sx;
        float v = 0.f;
        if ((unsigned)gz < 64u && (unsigned)gy < 64u && (unsigned)gx < 64u)
            v = g_pooled[((size_t)b*2 + icc)*SSS + gz*SS + gy*64 + gx];
        sh[s] = v;
    }
    __syncthreads();

    const int ly = tid >> 3, lx = tid & 7;
    float acc0[8], acc1[8];
    const float bias0 = bs[0], bias1 = bs[1];
#pragma unroll
    for (int z = 0; z < 8; z++) { acc0[z] = bias0; acc1[z] = bias1; }

#pragma unroll 1
    for (int icc = 0; icc < 2; icc++)
#pragma unroll 1
    for (int ky = 0; ky < 7; ky++)
#pragma unroll 1
    for (int kx = 0; kx < 7; kx++) {
        float col[14];
#pragma unroll
        for (int j = 0; j < 14; j++)
            col[j] = sh[icc*4312 + j*308 + (ly+ky)*14 + lx + kx];
#pragma unroll
        for (int kz = 0; kz < 7; kz++) {
            const float w0 = swt[icc*343 + kz*49 + ky*7 + kx];
            const float w1 = swt[686 + icc*343 + kz*49 + ky*7 + kx];
#pragma unroll
            for (int z = 0; z < 8; z++) {
                acc0[z] = fmaf(col[z+kz], w0, acc0[z]);
                acc1[z] = fmaf(col[z+kz], w1, acc1[z]);
            }
        }
    }

    float* g0 = g_gate + (size_t)b*2*SSS;
#pragma unroll
    for (int z = 0; z < 8; z++) {
        const int o = (z0+z)*SS + (y0+ly)*64 + (x0+lx);
        g0[o]       = 1.f/(1.f + __expf(-acc0[z]));
        g0[SSS + o] = 1.f/(1.f + __expf(-acc1[z]));
    }
}

// ---------------- combine: out = att1*g0 + att2*g1 + x ----------------------
// Thread handles 2 consecutive s for one channel, both batches.
__global__ __launch_bounds__(256) void k_combine(const float* __restrict__ x,
                                                 float* __restrict__ out) {
    const int i = blockIdx.x * 256 + threadIdx.x;      // 8,388,608 threads
    const int c = i >> 17;                              // SSS/2 per channel
    const int s = (i & 131071) << 1;
    const float4 a1 = *(const float4*)((const float*)g_att1 + ((size_t)c*SSS + s)*2);
    const float4 a2 = *(const float4*)((const float*)g_att2 + ((size_t)c*SSS + s)*2);

    // batch 0
    {
        const float2 xv = *(const float2*)(x + (size_t)c*SSS + s);
        const float2 g0 = *(const float2*)(g_gate + s);
        const float2 g1 = *(const float2*)(g_gate + SSS + s);
        float2 o;
        o.x = fmaf(a1.x, g0.x, fmaf(a2.x, g1.x, xv.x));
        o.y = fmaf(a1.z, g0.y, fmaf(a2.z, g1.y, xv.y));
        *(float2*)(out + (size_t)c*SSS + s) = o;
    }
    // batch 1
    {
        const float2 xv = *(const float2*)(x + (size_t)(CH + c)*SSS + s);
        const float2 g0 = *(const float2*)(g_gate + 2*SSS + s);
        const float2 g1 = *(const float2*)(g_gate + 3*SSS + s);
        float2 o;
        o.x = fmaf(a1.y, g0.x, fmaf(a2.y, g1.x, xv.x));
        o.y = fmaf(a1.w, g0.y, fmaf(a2.w, g1.y, xv.y));
        *(float2*)(out + (size_t)(CH + c)*SSS + s) = o;
    }
}

extern "C" void kernel_launch(void* const* d_in, const int* in_sizes, int n_in,
                              void* d_out, int out_size) {
    const float* x  = (const float*)d_in[0];
    const float* w1 = (const float*)d_in[1];
    const float* b1 = (const float*)d_in[2];
    const float* w2 = (const float*)d_in[3];
    const float* b2 = (const float*)d_in[4];
    const float* ws = (const float*)d_in[5];
    const float* bs = (const float*)d_in[6];
    float* out = (float*)d_out;

    k_conv1<<<dim3(128, 64), dim3(16, 16)>>>(x, w1, b1);
    k_conv2<<<dim3(243, 64), 128>>>(w2, b2);
    k_pool<<<1024, 256>>>();
    k_gate<<<dim3(256, 2), 128>>>(ws, bs);
    k_combine<<<32768, 256>>>(x, out);
}

// round 5
// speedup vs baseline: 1.2718x; 1.0825x over previous
#include <cuda_runtime.h>
#include <math.h>

#define SS   4096      // 64*64
#define SSS  262144    // 64^3
#define CH   64

typedef unsigned long long u64;

// Scratch (device globals). att1/att2 are batch-interleaved: element (c*SSS+s)
// is a float2 = (batch0, batch1). float4 decl for 16B alignment.
__device__ float4 g_att1[CH*SSS/2];
__device__ float4 g_att2[CH*SSS/2];
__device__ float2 g_pooled2[2*SSS];    // [ic={mean,max}][s] -> (b0,b1)
__device__ float  g_gate[2*2*SSS];     // [b][{g0,g1}][s]

__device__ __forceinline__ u64 pk2(float lo, float hi) {
    u64 r; asm("mov.b64 %0, {%1, %2};" : "=l"(r) : "f"(lo), "f"(hi)); return r;
}
__device__ __forceinline__ void ffma2(u64& d, u64 a, u64 b) {
    asm("fma.rn.f32x2 %0, %1, %2, %0;" : "+l"(d) : "l"(a), "l"(b));
}

// ---------------- conv1: depthwise 5x5x5, pad 2, both batches packed --------
// tile: z=8, y=16, x=16; thread computes a z-column of 8 packed outputs.
// Warp phase = 16 contiguous lx -> conflict-free LDS.64.
__global__ __launch_bounds__(256) void k_conv1(const float* __restrict__ x,
                                               const float* __restrict__ w1,
                                               const float* __restrict__ b1) {
    const int tile = blockIdx.x;                 // tz(8) ty(4) tx(4)
    const int c = blockIdx.y;
    const int tz = tile >> 4, ty = (tile >> 2) & 3, tx = tile & 3;
    const int z0 = tz * 8, y0 = ty * 16, x0 = tx * 16;

    __shared__ float2 sh[12*20*20];
    __shared__ float2 swt[125];

    const int tid = threadIdx.y * 16 + threadIdx.x;
    const float* __restrict__ x0p = x + (size_t)c * SSS;
    const float* __restrict__ x1p = x + (size_t)(CH + c) * SSS;

    if (tid < 125) { float w = w1[c*125 + tid]; swt[tid] = make_float2(w, w); }

    for (int s = tid; s < 12*20*20; s += 256) {
        int sz = s / 400, r = s % 400, sy = r / 20, sx = r % 20;
        int gz = z0 - 2 + sz, gy = y0 - 2 + sy, gx = x0 - 2 + sx;
        float2 v = make_float2(0.f, 0.f);
        if ((unsigned)gz < 64u && (unsigned)gy < 64u && (unsigned)gx < 64u) {
            int o = gz*SS + gy*64 + gx;
            v.x = x0p[o]; v.y = x1p[o];
        }
        sh[s] = v;
    }
    __syncthreads();

    const int lx = threadIdx.x, ly = threadIdx.y;
    u64 acc[8];
    const float bias = b1[c];
    const u64 bpk = pk2(bias, bias);
#pragma unroll
    for (int z = 0; z < 8; z++) acc[z] = bpk;

#pragma unroll 1
    for (int ky = 0; ky < 5; ky++) {
        const int rowb = (ly + ky) * 20 + lx;
#pragma unroll
        for (int kx = 0; kx < 5; kx++) {
            u64 col[12];
#pragma unroll
            for (int j = 0; j < 12; j++)
                col[j] = *(const u64*)&sh[j*400 + rowb + kx];
#pragma unroll
            for (int kz = 0; kz < 5; kz++) {
                const u64 w = *(const u64*)&swt[kz*25 + ky*5 + kx];
#pragma unroll
                for (int z = 0; z < 8; z++)
                    ffma2(acc[z], col[z+kz], w);
            }
        }
    }

    float2* __restrict__ oc = (float2*)g_att1 + (size_t)c * SSS;
#pragma unroll
    for (int z = 0; z < 8; z++)
        *(u64*)&oc[(z0+z)*SS + (y0+ly)*64 + (x0+lx)] = acc[z];
}

// ---------------- conv2: depthwise 7x7x7, dilation 3, pad 9 -----------------
// Residue decomposition (mod 3) -> dense 7-tap conv on subsampled grid.
// smem: x-stride 14 float2, z-plane stride padded to C2_ZS=200 float2.
// Thread map: lx=tid&7, hz=(tid>>3)&1, ly=tid>>4. A 16-lane phase holds
// lx(0..7) x hz(0..1); phase addr mod 16 = lx + 8*hz (11*200=2200===8 mod 16)
// -> 16 distinct bank pairs -> conflict-free LDS.64. 47.5 KB static smem.
#define C2_ZS 200
__global__ __launch_bounds__(128) void k_conv2(const float* __restrict__ w2,
                                               const float* __restrict__ b2) {
    __shared__ float2 sh[28*C2_ZS];              // 44800 B
    __shared__ float2 swt[343];                  // 2744 B

    const int blk = blockIdx.x;                  // 27 residues * 9 yx tiles
    const int c = blockIdx.y;
    const int res = blk / 9, t = blk % 9;
    const int rz = res / 9, ry = (res / 3) % 3, rx = res % 3;
    const int tyi = t / 3, txi = t % 3;
    const int Lz = (rz == 0) ? 22 : 21;
    const int Ly = (ry == 0) ? 22 : 21;
    const int Lx = (rx == 0) ? 22 : 21;

    const int tid = threadIdx.x;
    const float2* __restrict__ icp = (const float2*)g_att1 + (size_t)c * SSS;
    for (int s = tid; s < 343; s += 128) { float w = w2[c*343 + s]; swt[s] = make_float2(w, w); }

    const int uy0 = tyi*8, ux0 = txi*8;
    for (int s = tid; s < 28*14*14; s += 128) {
        int sz = s / 196, r = s % 196, sy = r / 14, sx = r % 14;
        int gz = rz + 3*(sz - 3);
        int gy = ry + 3*(uy0 + sy - 3);
        int gx = rx + 3*(ux0 + sx - 3);
        float2 v = make_float2(0.f, 0.f);
        if ((unsigned)gz < 64u && (unsigned)gy < 64u && (unsigned)gx < 64u)
            v = icp[gz*SS + gy*64 + gx];
        sh[sz*C2_ZS + sy*14 + sx] = v;
    }
    __syncthreads();

    const int lx = tid & 7;
    const int hz = (tid >> 3) & 1;               // z half: u 0..10 / 11..21
    const int ly = tid >> 4;                     // 0..7
    const int uy = uy0 + ly, ux = ux0 + lx;
    const int zb = 11*hz;

    u64 acc[11];
    const float bias = b2[c];
    const u64 bpk = pk2(bias, bias);
#pragma unroll
    for (int l = 0; l < 11; l++) acc[l] = bpk;

#pragma unroll 1
    for (int ky = 0; ky < 7; ky++) {
        const int rowb = (ly + ky)*14 + lx;
#pragma unroll
        for (int kx = 0; kx < 7; kx++) {
            u64 col[17];
#pragma unroll
            for (int j = 0; j < 17; j++)
                col[j] = *(const u64*)&sh[(zb + j)*C2_ZS + rowb + kx];
#pragma unroll
            for (int kz = 0; kz < 7; kz++) {
                const u64 w = *(const u64*)&swt[kz*49 + ky*7 + kx];
#pragma unroll
                for (int l = 0; l < 11; l++)
                    ffma2(acc[l], col[l+kz], w);
            }
        }
    }

    if (uy < Ly && ux < Lx) {
        float2* __restrict__ oc = (float2*)g_att2 + (size_t)c*SSS;
        const int gy = ry + 3*uy, gx = rx + 3*ux;
#pragma unroll
        for (int l = 0; l < 11; l++) {
            const int u = zb + l;
            if (u < Lz)
                *(u64*)&oc[(rz + 3*u)*SS + gy*64 + gx] = acc[l];
        }
    }
}

// ---------------- pool: channel mean + max over [att1; att2], both batches --
__global__ __launch_bounds__(256) void k_pool() {
    const int s = blockIdx.x * 256 + threadIdx.x;       // over SSS
    const float2* p1 = (const float2*)g_att1 + s;
    const float2* p2 = (const float2*)g_att2 + s;
    float s0 = 0.f, s1 = 0.f, m0 = -INFINITY, m1 = -INFINITY;
#pragma unroll 8
    for (int c = 0; c < 64; c++) {
        float2 v = p1[(size_t)c*SSS];
        s0 += v.x; s1 += v.y; m0 = fmaxf(m0, v.x); m1 = fmaxf(m1, v.y);
    }
#pragma unroll 8
    for (int c = 0; c < 64; c++) {
        float2 v = p2[(size_t)c*SSS];
        s0 += v.x; s1 += v.y; m0 = fmaxf(m0, v.x); m1 = fmaxf(m1, v.y);
    }
    g_pooled2[s]       = make_float2(s0 * (1.f/128.f), s1 * (1.f/128.f));
    g_pooled2[SSS + s] = make_float2(m0, m1);
}

// ---------------- gate: 2->2 conv 7x7x7 pad 3, sigmoid (scalar, per batch) --
// Known-good scalar version; 40 KB static smem.
__global__ __launch_bounds__(128) void k_gate(const float* __restrict__ ws,
                                              const float* __restrict__ bs) {
    const int tile = blockIdx.x;                 // tz(8) ty(4) tx(8) = 256
    const int b = blockIdx.y;
    const int tz = tile >> 5, ty = (tile >> 3) & 3, tx = tile & 7;
    const int z0 = tz*8, y0 = ty*16, x0 = tx*8;

    __shared__ float sh[2*14*22*14];
    __shared__ float swt[1372];
    const int tid = threadIdx.x;

    for (int s = tid; s < 1372; s += 128) swt[s] = ws[s];
    for (int s = tid; s < 2*14*22*14; s += 128) {
        int icc = s / 4312, r = s % 4312;
        int sz = r / 308, r2 = r % 308, sy = r2 / 14, sx = r2 % 14;
        int gz = z0-3+sz, gy = y0-3+sy, gx = x0-3+sx;
        float v = 0.f;
        if ((unsigned)gz < 64u && (unsigned)gy < 64u && (unsigned)gx < 64u) {
            float2 p = g_pooled2[icc*SSS + gz*SS + gy*64 + gx];
            v = b ? p.y : p.x;
        }
        sh[s] = v;
    }
    __syncthreads();

    const int ly = tid >> 3, lx = tid & 7;
    float acc0[8], acc1[8];
    const float bias0 = bs[0], bias1 = bs[1];
#pragma unroll
    for (int z = 0; z < 8; z++) { acc0[z] = bias0; acc1[z] = bias1; }

#pragma unroll 1
    for (int icc = 0; icc < 2; icc++)
#pragma unroll 1
    for (int ky = 0; ky < 7; ky++)
#pragma unroll 1
    for (int kx = 0; kx < 7; kx++) {
        float col[14];
#pragma unroll
        for (int j = 0; j < 14; j++)
            col[j] = sh[icc*4312 + j*308 + (ly+ky)*14 + lx + kx];
#pragma unroll
        for (int kz = 0; kz < 7; kz++) {
            const float w0 = swt[icc*343 + kz*49 + ky*7 + kx];
            const float w1 = swt[686 + icc*343 + kz*49 + ky*7 + kx];
#pragma unroll
            for (int z = 0; z < 8; z++) {
                acc0[z] = fmaf(col[z+kz], w0, acc0[z]);
                acc1[z] = fmaf(col[z+kz], w1, acc1[z]);
            }
        }
    }

    float* g0 = g_gate + (size_t)b*2*SSS;
#pragma unroll
    for (int z = 0; z < 8; z++) {
        const int o = (z0+z)*SS + (y0+ly)*64 + (x0+lx);
        g0[o]       = 1.f/(1.f + __expf(-acc0[z]));
        g0[SSS + o] = 1.f/(1.f + __expf(-acc1[z]));
    }
}

// ---------------- combine: out = att1*g0 + att2*g1 + x ----------------------
__global__ __launch_bounds__(256) void k_combine(const float* __restrict__ x,
                                                 float* __restrict__ out) {
    const int i = blockIdx.x * 256 + threadIdx.x;      // 8,388,608 threads
    const int c = i >> 17;                              // SSS/2 per channel
    const int s = (i & 131071) << 1;
    const float4 a1 = *(const float4*)((const float*)g_att1 + ((size_t)c*SSS + s)*2);
    const float4 a2 = *(const float4*)((const float*)g_att2 + ((size_t)c*SSS + s)*2);

    // batch 0
    {
        const float2 xv = *(const float2*)(x + (size_t)c*SSS + s);
        const float2 g0 = *(const float2*)(g_gate + s);
        const float2 g1 = *(const float2*)(g_gate + SSS + s);
        float2 o;
        o.x = fmaf(a1.x, g0.x, fmaf(a2.x, g1.x, xv.x));
        o.y = fmaf(a1.z, g0.y, fmaf(a2.z, g1.y, xv.y));
        *(float2*)(out + (size_t)c*SSS + s) = o;
    }
    // batch 1
    {
        const float2 xv = *(const float2*)(x + (size_t)(CH + c)*SSS + s);
        const float2 g0 = *(const float2*)(g_gate + 2*SSS + s);
        const float2 g1 = *(const float2*)(g_gate + 3*SSS + s);
        float2 o;
        o.x = fmaf(a1.y, g0.x, fmaf(a2.y, g1.x, xv.x));
        o.y = fmaf(a1.w, g0.y, fmaf(a2.w, g1.y, xv.y));
        *(float2*)(out + (size_t)(CH + c)*SSS + s) = o;
    }
}

extern "C" void kernel_launch(void* const* d_in, const int* in_sizes, int n_in,
                              void* d_out, int out_size) {
    const float* x  = (const float*)d_in[0];
    const float* w1 = (const float*)d_in[1];
    const float* b1 = (const float*)d_in[2];
    const float* w2 = (const float*)d_in[3];
    const float* b2 = (const float*)d_in[4];
    const float* ws = (const float*)d_in[5];
    const float* bs = (const float*)d_in[6];
    float* out = (float*)d_out;

    k_conv1<<<dim3(128, 64), dim3(16, 16)>>>(x, w1, b1);
    k_conv2<<<dim3(243, 64), 128>>>(w2, b2);
    k_pool<<<1024, 256>>>();
    k_gate<<<dim3(256, 2), 128>>>(ws, bs);
    k_combine<<<32768, 256>>>(x, out);
}

// round 6
// speedup vs baseline: 1.2722x; 1.0003x over previous
#include <cuda_runtime.h>
#include <math.h>

#define SS   4096      // 64*64
#define SSS  262144    // 64^3
#define CH   64

typedef unsigned long long u64;

// Scratch (device globals). att1/att2 are batch-interleaved: element (c*SSS+s)
// is a float2 = (batch0, batch1). float4 decl for 16B alignment.
__device__ float4 g_att1[CH*SSS/2];
__device__ float4 g_att2[CH*SSS/2];
__device__ float2 g_pooled2[2*SSS];    // [ic={mean,max}][s] -> (b0,b1)
__device__ float  g_gate[2*2*SSS];     // [b][{g0,g1}][s]

__device__ __forceinline__ u64 pk2(float lo, float hi) {
    u64 r; asm("mov.b64 %0, {%1, %2};" : "=l"(r) : "f"(lo), "f"(hi)); return r;
}
__device__ __forceinline__ void ffma2(u64& d, u64 a, u64 b) {
    asm("fma.rn.f32x2 %0, %1, %2, %0;" : "+l"(d) : "l"(a), "l"(b));
}

// ---------------- conv1: depthwise 5x5x5, pad 2, both batches packed --------
// tile: z=8, y=16, x=16; thread computes a z-column of 8 packed outputs.
// Warp phase = 16 contiguous lx -> conflict-free LDS.64.
__global__ __launch_bounds__(256) void k_conv1(const float* __restrict__ x,
                                               const float* __restrict__ w1,
                                               const float* __restrict__ b1) {
    const int tile = blockIdx.x;                 // tz(8) ty(4) tx(4)
    const int c = blockIdx.y;
    const int tz = tile >> 4, ty = (tile >> 2) & 3, tx = tile & 3;
    const int z0 = tz * 8, y0 = ty * 16, x0 = tx * 16;

    __shared__ float2 sh[12*20*20];
    __shared__ float2 swt[125];

    const int tid = threadIdx.y * 16 + threadIdx.x;
    const float* __restrict__ x0p = x + (size_t)c * SSS;
    const float* __restrict__ x1p = x + (size_t)(CH + c) * SSS;

    if (tid < 125) { float w = w1[c*125 + tid]; swt[tid] = make_float2(w, w); }

    for (int s = tid; s < 12*20*20; s += 256) {
        int sz = s / 400, r = s % 400, sy = r / 20, sx = r % 20;
        int gz = z0 - 2 + sz, gy = y0 - 2 + sy, gx = x0 - 2 + sx;
        float2 v = make_float2(0.f, 0.f);
        if ((unsigned)gz < 64u && (unsigned)gy < 64u && (unsigned)gx < 64u) {
            int o = gz*SS + gy*64 + gx;
            v.x = x0p[o]; v.y = x1p[o];
        }
        sh[s] = v;
    }
    __syncthreads();

    const int lx = threadIdx.x, ly = threadIdx.y;
    u64 acc[8];
    const float bias = b1[c];
    const u64 bpk = pk2(bias, bias);
#pragma unroll
    for (int z = 0; z < 8; z++) acc[z] = bpk;

#pragma unroll 1
    for (int ky = 0; ky < 5; ky++) {
        const int rowb = (ly + ky) * 20 + lx;
#pragma unroll
        for (int kx = 0; kx < 5; kx++) {
            u64 col[12];
#pragma unroll
            for (int j = 0; j < 12; j++)
                col[j] = *(const u64*)&sh[j*400 + rowb + kx];
#pragma unroll
            for (int kz = 0; kz < 5; kz++) {
                const u64 w = *(const u64*)&swt[kz*25 + ky*5 + kx];
#pragma unroll
                for (int z = 0; z < 8; z++)
                    ffma2(acc[z], col[z+kz], w);
            }
        }
    }

    float2* __restrict__ oc = (float2*)g_att1 + (size_t)c * SSS;
#pragma unroll
    for (int z = 0; z < 8; z++)
        *(u64*)&oc[(z0+z)*SS + (y0+ly)*64 + (x0+lx)] = acc[z];
}

// ---------------- conv2: depthwise 7x7x7, dilation 3, pad 9 -----------------
// Residue decomposition (mod 3) -> dense 7-tap conv on subsampled grid.
// smem: x-stride 14 float2, z-plane stride padded to C2_ZS=200 float2.
// Thread map: lx=tid&7, hz=(tid>>3)&1, ly=tid>>4. A 16-lane phase holds
// lx(0..7) x hz(0..1); phase addr mod 16 = lx + 8*hz (11*200=2200===8 mod 16)
// -> 16 distinct bank pairs -> conflict-free LDS.64. 47.5 KB static smem.
#define C2_ZS 200
__global__ __launch_bounds__(128) void k_conv2(const float* __restrict__ w2,
                                               const float* __restrict__ b2) {
    __shared__ float2 sh[28*C2_ZS];              // 44800 B
    __shared__ float2 swt[343];                  // 2744 B

    const int blk = blockIdx.x;                  // 27 residues * 9 yx tiles
    const int c = blockIdx.y;
    const int res = blk / 9, t = blk % 9;
    const int rz = res / 9, ry = (res / 3) % 3, rx = res % 3;
    const int tyi = t / 3, txi = t % 3;
    const int Lz = (rz == 0) ? 22 : 21;
    const int Ly = (ry == 0) ? 22 : 21;
    const int Lx = (rx == 0) ? 22 : 21;

    const int tid = threadIdx.x;
    const float2* __restrict__ icp = (const float2*)g_att1 + (size_t)c * SSS;
    for (int s = tid; s < 343; s += 128) { float w = w2[c*343 + s]; swt[s] = make_float2(w, w); }

    const int uy0 = tyi*8, ux0 = txi*8;
    for (int s = tid; s < 28*14*14; s += 128) {
        int sz = s / 196, r = s % 196, sy = r / 14, sx = r % 14;
        int gz = rz + 3*(sz - 3);
        int gy = ry + 3*(uy0 + sy - 3);
        int gx = rx + 3*(ux0 + sx - 3);
        float2 v = make_float2(0.f, 0.f);
        if ((unsigned)gz < 64u && (unsigned)gy < 64u && (unsigned)gx < 64u)
            v = icp[gz*SS + gy*64 + gx];
        sh[sz*C2_ZS + sy*14 + sx] = v;
    }
    __syncthreads();

    const int lx = tid & 7;
    const int hz = (tid >> 3) & 1;               // z half: u 0..10 / 11..21
    const int ly = tid >> 4;                     // 0..7
    const int uy = uy0 + ly, ux = ux0 + lx;
    const int zb = 11*hz;

    u64 acc[11];
    const float bias = b2[c];
    const u64 bpk = pk2(bias, bias);
#pragma unroll
    for (int l = 0; l < 11; l++) acc[l] = bpk;

#pragma unroll 1
    for (int ky = 0; ky < 7; ky++) {
        const int rowb = (ly + ky)*14 + lx;
#pragma unroll
        for (int kx = 0; kx < 7; kx++) {
            u64 col[17];
#pragma unroll
            for (int j = 0; j < 17; j++)
                col[j] = *(const u64*)&sh[(zb + j)*C2_ZS + rowb + kx];
#pragma unroll
            for (int kz = 0; kz < 7; kz++) {
                const u64 w = *(const u64*)&swt[kz*49 + ky*7 + kx];
#pragma unroll
                for (int l = 0; l < 11; l++)
                    ffma2(acc[l], col[l+kz], w);
            }
        }
    }

    if (uy < Ly && ux < Lx) {
        float2* __restrict__ oc = (float2*)g_att2 + (size_t)c*SSS;
        const int gy = ry + 3*uy, gx = rx + 3*ux;
#pragma unroll
        for (int l = 0; l < 11; l++) {
            const int u = zb + l;
            if (u < Lz)
                *(u64*)&oc[(rz + 3*u)*SS + gy*64 + gx] = acc[l];
        }
    }
}

// ---------------- pool: channel mean + max over [att1; att2], both batches --
__global__ __launch_bounds__(256) void k_pool() {
    const int s = blockIdx.x * 256 + threadIdx.x;       // over SSS
    const float2* p1 = (const float2*)g_att1 + s;
    const float2* p2 = (const float2*)g_att2 + s;
    float s0 = 0.f, s1 = 0.f, m0 = -INFINITY, m1 = -INFINITY;
#pragma unroll 8
    for (int c = 0; c < 64; c++) {
        float2 v = p1[(size_t)c*SSS];
        s0 += v.x; s1 += v.y; m0 = fmaxf(m0, v.x); m1 = fmaxf(m1, v.y);
    }
#pragma unroll 8
    for (int c = 0; c < 64; c++) {
        float2 v = p2[(size_t)c*SSS];
        s0 += v.x; s1 += v.y; m0 = fmaxf(m0, v.x); m1 = fmaxf(m1, v.y);
    }
    g_pooled2[s]       = make_float2(s0 * (1.f/128.f), s1 * (1.f/128.f));
    g_pooled2[SSS + s] = make_float2(m0, m1);
}

// ---------------- gate: 2->2 conv 7x7x7 pad 3, sigmoid (scalar, per batch) --
// Known-good scalar version; 40 KB static smem.
__global__ __launch_bounds__(128) void k_gate(const float* __restrict__ ws,
                                              const float* __restrict__ bs) {
    const int tile = blockIdx.x;                 // tz(8) ty(4) tx(8) = 256
    const int b = blockIdx.y;
    const int tz = tile >> 5, ty = (tile >> 3) & 3, tx = tile & 7;
    const int z0 = tz*8, y0 = ty*16, x0 = tx*8;

    __shared__ float sh[2*14*22*14];
    __shared__ float swt[1372];
    const int tid = threadIdx.x;

    for (int s = tid; s < 1372; s += 128) swt[s] = ws[s];
    for (int s = tid; s < 2*14*22*14; s += 128) {
        int icc = s / 4312, r = s % 4312;
        int sz = r / 308, r2 = r % 308, sy = r2 / 14, sx = r2 % 14;
        int gz = z0-3+sz, gy = y0-3+sy, gx = x0-3+sx;
        float v = 0.f;
        if ((unsigned)gz < 64u && (unsigned)gy < 64u && (unsigned)gx < 64u) {
            float2 p = g_pooled2[icc*SSS + gz*SS + gy*64 + gx];
            v = b ? p.y : p.x;
        }
        sh[s] = v;
    }
    __syncthreads();

    const int ly = tid >> 3, lx = tid & 7;
    float acc0[8], acc1[8];
    const float bias0 = bs[0], bias1 = bs[1];
#pragma unroll
    for (int z = 0; z < 8; z++) { acc0[z] = bias0; acc1[z] = bias1; }

#pragma unroll 1
    for (int icc = 0; icc < 2; icc++)
#pragma unroll 1
    for (int ky = 0; ky < 7; ky++)
#pragma unroll 1
    for (int kx = 0; kx < 7; kx++) {
        float col[14];
#pragma unroll
        for (int j = 0; j < 14; j++)
            col[j] = sh[icc*4312 + j*308 + (ly+ky)*14 + lx + kx];
#pragma unroll
        for (int kz = 0; kz < 7; kz++) {
            const float w0 = swt[icc*343 + kz*49 + ky*7 + kx];
            const float w1 = swt[686 + icc*343 + kz*49 + ky*7 + kx];
#pragma unroll
            for (int z = 0; z < 8; z++) {
                acc0[z] = fmaf(col[z+kz], w0, acc0[z]);
                acc1[z] = fmaf(col[z+kz], w1, acc1[z]);
            }
        }
    }

    float* g0 = g_gate + (size_t)b*2*SSS;
#pragma unroll
    for (int z = 0; z < 8; z++) {
        const int o = (z0+z)*SS + (y0+ly)*64 + (x0+lx);
        g0[o]       = 1.f/(1.f + __expf(-acc0[z]));
        g0[SSS + o] = 1.f/(1.f + __expf(-acc1[z]));
    }
}

// ---------------- combine: out = att1*g0 + att2*g1 + x ----------------------
__global__ __launch_bounds__(256) void k_combine(const float* __restrict__ x,
                                                 float* __restrict__ out) {
    const int i = blockIdx.x * 256 + threadIdx.x;      // 8,388,608 threads
    const int c = i >> 17;                              // SSS/2 per channel
    const int s = (i & 131071) << 1;
    const float4 a1 = *(const float4*)((const float*)g_att1 + ((size_t)c*SSS + s)*2);
    const float4 a2 = *(const float4*)((const float*)g_att2 + ((size_t)c*SSS + s)*2);

    // batch 0
    {
        const float2 xv = *(const float2*)(x + (size_t)c*SSS + s);
        const float2 g0 = *(const float2*)(g_gate + s);
        const float2 g1 = *(const float2*)(g_gate + SSS + s);
        float2 o;
        o.x = fmaf(a1.x, g0.x, fmaf(a2.x, g1.x, xv.x));
        o.y = fmaf(a1.z, g0.y, fmaf(a2.z, g1.y, xv.y));
        *(float2*)(out + (size_t)c*SSS + s) = o;
    }
    // batch 1
    {
        const float2 xv = *(const float2*)(x + (size_t)(CH + c)*SSS + s);
        const float2 g0 = *(const float2*)(g_gate + 2*SSS + s);
        const float2 g1 = *(const float2*)(g_gate + 3*SSS + s);
        float2 o;
        o.x = fmaf(a1.y, g0.x, fmaf(a2.y, g1.x, xv.x));
        o.y = fmaf(a1.w, g0.y, fmaf(a2.w, g1.y, xv.y));
        *(float2*)(out + (size_t)(CH + c)*SSS + s) = o;
    }
}

extern "C" void kernel_launch(void* const* d_in, const int* in_sizes, int n_in,
                              void* d_out, int out_size) {
    const float* x  = (const float*)d_in[0];
    const float* w1 = (const float*)d_in[1];
    const float* b1 = (const float*)d_in[2];
    const float* w2 = (const float*)d_in[3];
    const float* b2 = (const float*)d_in[4];
    const float* ws = (const float*)d_in[5];
    const float* bs = (const float*)d_in[6];
    float* out = (float*)d_out;

    k_conv1<<<dim3(128, 64), dim3(16, 16)>>>(x, w1, b1);
    k_conv2<<<dim3(243, 64), 128>>>(w2, b2);
    k_pool<<<1024, 256>>>();
    k_gate<<<dim3(256, 2), 128>>>(ws, bs);
    k_combine<<<32768, 256>>>(x, out);
}